// round 1
// baseline (speedup 1.0000x reference)
#include <cuda_runtime.h>
#include <math.h>

// Problem constants
#define BB      2
#define SS      2048
#define DM      1024
#define NH      16
#define DK      64
#define DFF     4096
#define BS      (BB*SS)               // 4096 rows
#define OUT_ELEMS ((long long)BS*DM)              // 4194304
#define ATT_ELEMS ((long long)BB*NH*SS*SS)        // 134217728

// ---------------- scratch (no allocation allowed -> __device__ globals) ----
__device__ float g_Q  [BS*DM];
__device__ float g_K  [BS*DM];
__device__ float g_V  [BS*DM];
__device__ float g_ctx[BS*DM];
__device__ float g_h  [BS*DM];
__device__ float g_tmp[BS*DM];
__device__ float g_ff [(long long)BS*DFF];
// fallback attn buffer in case the harness output only holds `out`
__device__ float g_attn_fb[ATT_ELEMS];

// ---------------------------------------------------------------------------
// Generic register-blocked SGEMM.  C = act(alpha*A@B(^T) + bias + res)
// Assumes M % BM == 0, N % BN == 0, K % BK == 0 (true for every call here).
// Batched via blockIdx.z with split offsets: off = (z%HH)*si + (z/HH)*so.
// ---------------------------------------------------------------------------
__device__ __forceinline__ float gelu_exact(float v) {
    return 0.5f * v * (1.0f + erff(v * 0.70710678118654752f));
}

template<int BM, int BN, int BK, int TM, int TN, bool TRANSB, int ACT>
__global__ void __launch_bounds__(256)
gemm_k(const float* __restrict__ A, const float* __restrict__ Bm,
       float* __restrict__ C,
       int M, int N, int K, int lda, int ldb, int ldc,
       float alpha,
       const float* __restrict__ bias,
       const float* __restrict__ res,
       int HH,
       long long sAi, long long sAo,
       long long sBi, long long sBo,
       long long sCi, long long sCo)
{
    constexpr int THREADS = (BM / TM) * (BN / TN);   // must be 256
    __shared__ float As[BK][BM];
    __shared__ float Bs[BK][BN];

    const int z  = blockIdx.z;
    const int zi = z % HH, zo = z / HH;
    A  += zi * sAi + zo * sAo;
    Bm += zi * sBi + zo * sBo;
    C  += zi * sCi + zo * sCo;
    const float* Rp = res ? (res + zi * sCi + zo * sCo) : nullptr;

    const int m0  = blockIdx.y * BM;
    const int n0  = blockIdx.x * BN;
    const int tid = threadIdx.x;
    const int tx  = tid % (BN / TN);
    const int ty  = tid / (BN / TN);

    float acc[TM][TN];
#pragma unroll
    for (int i = 0; i < TM; i++)
#pragma unroll
        for (int j = 0; j < TN; j++) acc[i][j] = 0.0f;

    for (int k0 = 0; k0 < K; k0 += BK) {
        // load A tile (BM x BK), stored transposed As[k][m]
#pragma unroll
        for (int idx = tid; idx < BM * BK; idx += THREADS) {
            int m = idx / BK, k = idx % BK;
            As[k][m] = A[(size_t)(m0 + m) * lda + (k0 + k)];
        }
        // load B tile
        if (TRANSB) {
#pragma unroll
            for (int idx = tid; idx < BN * BK; idx += THREADS) {
                int n = idx / BK, k = idx % BK;
                Bs[k][n] = Bm[(size_t)(n0 + n) * ldb + (k0 + k)];
            }
        } else {
#pragma unroll
            for (int idx = tid; idx < BK * BN; idx += THREADS) {
                int k = idx / BN, n = idx % BN;
                Bs[k][n] = Bm[(size_t)(k0 + k) * ldb + (n0 + n)];
            }
        }
        __syncthreads();

#pragma unroll
        for (int kk = 0; kk < BK; kk++) {
            float ra[TM], rb[TN];
            const float4* a4 = reinterpret_cast<const float4*>(&As[kk][ty * TM]);
#pragma unroll
            for (int i = 0; i < TM / 4; i++) {
                float4 t = a4[i];
                ra[4*i+0] = t.x; ra[4*i+1] = t.y; ra[4*i+2] = t.z; ra[4*i+3] = t.w;
            }
            const float4* b4 = reinterpret_cast<const float4*>(&Bs[kk][tx * TN]);
#pragma unroll
            for (int j = 0; j < TN / 4; j++) {
                float4 t = b4[j];
                rb[4*j+0] = t.x; rb[4*j+1] = t.y; rb[4*j+2] = t.z; rb[4*j+3] = t.w;
            }
#pragma unroll
            for (int i = 0; i < TM; i++)
#pragma unroll
                for (int j = 0; j < TN; j++)
                    acc[i][j] = fmaf(ra[i], rb[j], acc[i][j]);
        }
        __syncthreads();
    }

    // epilogue
#pragma unroll
    for (int i = 0; i < TM; i++) {
        const int m = m0 + ty * TM + i;
#pragma unroll
        for (int j = 0; j < TN; j++) {
            const int n = n0 + tx * TN + j;
            float v = acc[i][j] * alpha;
            if (bias) v += bias[n];
            if (Rp)   v += Rp[(size_t)m * ldc + n];
            if (ACT == 1) v = gelu_exact(v);
            C[(size_t)m * ldc + n] = v;
        }
    }
}

// ---------------------------------------------------------------------------
// Row softmax over S=2048 elems, in place. One block per row, 256 threads.
// Row data staged in smem so exp() results aren't recomputed.
// ---------------------------------------------------------------------------
__global__ void __launch_bounds__(256) softmax_k(float* __restrict__ attn)
{
    const int tid = threadIdx.x;
    const long long row = blockIdx.x;
    float* p = attn + row * (long long)SS;

    __shared__ float buf[SS];          // 8 KB
    __shared__ float redm[8];
    __shared__ float reds[8];

    float lm = -3.4e38f;
#pragma unroll
    for (int i = 0; i < SS / 256; i++) {
        float v = p[tid + i * 256];
        buf[tid + i * 256] = v;
        lm = fmaxf(lm, v);
    }
#pragma unroll
    for (int o = 16; o > 0; o >>= 1)
        lm = fmaxf(lm, __shfl_xor_sync(0xffffffffu, lm, o));
    if ((tid & 31) == 0) redm[tid >> 5] = lm;
    __syncthreads();
    if (tid < 8) {
        float v = redm[tid];
#pragma unroll
        for (int o = 4; o > 0; o >>= 1)
            v = fmaxf(v, __shfl_xor_sync(0xffu, v, o));
        if (tid == 0) redm[0] = v;
    }
    __syncthreads();
    const float mx = redm[0];

    float ls = 0.0f;
#pragma unroll
    for (int i = 0; i < SS / 256; i++) {
        int idx = tid + i * 256;
        float e = expf(buf[idx] - mx);
        buf[idx] = e;
        ls += e;
    }
#pragma unroll
    for (int o = 16; o > 0; o >>= 1)
        ls += __shfl_xor_sync(0xffffffffu, ls, o);
    if ((tid & 31) == 0) reds[tid >> 5] = ls;
    __syncthreads();
    if (tid < 8) {
        float v = reds[tid];
#pragma unroll
        for (int o = 4; o > 0; o >>= 1)
            v += __shfl_xor_sync(0xffu, v, o);
        if (tid == 0) reds[0] = v;
    }
    __syncthreads();
    const float inv = 1.0f / reds[0];
#pragma unroll
    for (int i = 0; i < SS / 256; i++) {
        int idx = tid + i * 256;
        p[idx] = buf[idx] * inv;
    }
}

// ---------------------------------------------------------------------------
// LayerNorm over D=1024, one block (256 threads) per row. EPS = 1e-5.
// ---------------------------------------------------------------------------
__global__ void __launch_bounds__(256)
ln_k(const float* __restrict__ in, const float* __restrict__ gam,
     const float* __restrict__ bet, float* __restrict__ out)
{
    const int row = blockIdx.x;
    const int tid = threadIdx.x;
    const float* p = in + (size_t)row * DM;

    float v[4];
    float s = 0.0f, ss = 0.0f;
#pragma unroll
    for (int i = 0; i < 4; i++) {
        v[i] = p[tid + i * 256];
        s  += v[i];
        ss += v[i] * v[i];
    }
    __shared__ float r1[8], r2[8];
#pragma unroll
    for (int o = 16; o > 0; o >>= 1) {
        s  += __shfl_xor_sync(0xffffffffu, s,  o);
        ss += __shfl_xor_sync(0xffffffffu, ss, o);
    }
    if ((tid & 31) == 0) { r1[tid >> 5] = s; r2[tid >> 5] = ss; }
    __syncthreads();
    if (tid < 8) {
        float a = r1[tid], b = r2[tid];
#pragma unroll
        for (int o = 4; o > 0; o >>= 1) {
            a += __shfl_xor_sync(0xffu, a, o);
            b += __shfl_xor_sync(0xffu, b, o);
        }
        if (tid == 0) { r1[0] = a; r2[0] = b; }
    }
    __syncthreads();
    const float mean = r1[0] * (1.0f / DM);
    const float var  = r2[0] * (1.0f / DM) - mean * mean;
    const float rstd = rsqrtf(var + 1e-5f);
    float* o = out + (size_t)row * DM;
#pragma unroll
    for (int i = 0; i < 4; i++) {
        int c = tid + i * 256;
        o[c] = (v[i] - mean) * rstd * gam[c] + bet[c];
    }
}

// ---------------------------------------------------------------------------
extern "C" void kernel_launch(void* const* d_in, const int* in_sizes, int n_in,
                              void* d_out, int out_size)
{
    const float* x    = (const float*)d_in[0];
    const float* w_q  = (const float*)d_in[1];
    const float* w_k  = (const float*)d_in[2];
    const float* w_v  = (const float*)d_in[3];
    const float* w_o  = (const float*)d_in[4];
    const float* b_o  = (const float*)d_in[5];
    const float* w1   = (const float*)d_in[6];
    const float* b1   = (const float*)d_in[7];
    const float* w2   = (const float*)d_in[8];
    const float* b2   = (const float*)d_in[9];
    const float* ln1g = (const float*)d_in[10];
    const float* ln1b = (const float*)d_in[11];
    const float* ln2g = (const float*)d_in[12];
    const float* ln2b = (const float*)d_in[13];
    float* out = (float*)d_out;

    float *Q, *K, *V, *ctx, *h, *tmp, *ff, *attn_fb;
    cudaGetSymbolAddress((void**)&Q,      g_Q);
    cudaGetSymbolAddress((void**)&K,      g_K);
    cudaGetSymbolAddress((void**)&V,      g_V);
    cudaGetSymbolAddress((void**)&ctx,    g_ctx);
    cudaGetSymbolAddress((void**)&h,      g_h);
    cudaGetSymbolAddress((void**)&tmp,    g_tmp);
    cudaGetSymbolAddress((void**)&ff,     g_ff);
    cudaGetSymbolAddress((void**)&attn_fb, g_attn_fb);

    // attn lives in d_out right after `out` when the harness holds the tuple
    float* attn = ((long long)out_size >= OUT_ELEMS + ATT_ELEMS)
                      ? (out + OUT_ELEMS) : attn_fb;

    const dim3 thr(256);

    // 1) QKV projections: [4096,1024] = x @ W  (M=4096,N=1024,K=1024)
    {
        dim3 grid(DM / 128, BS / 128, 1);
        gemm_k<128,128,8,8,8,false,0><<<grid, thr>>>(
            x, w_q, Q, BS, DM, DM, DM, DM, DM, 1.0f, nullptr, nullptr,
            1, 0,0, 0,0, 0,0);
        gemm_k<128,128,8,8,8,false,0><<<grid, thr>>>(
            x, w_k, K, BS, DM, DM, DM, DM, DM, 1.0f, nullptr, nullptr,
            1, 0,0, 0,0, 0,0);
        gemm_k<128,128,8,8,8,false,0><<<grid, thr>>>(
            x, w_v, V, BS, DM, DM, DM, DM, DM, 1.0f, nullptr, nullptr,
            1, 0,0, 0,0, 0,0);
    }

    // 2) scores = Q_h @ K_h^T / sqrt(64), batched over 32 (b,h)
    {
        dim3 grid(SS / 128, SS / 128, BB * NH);
        gemm_k<128,128,8,8,8,true,0><<<grid, thr>>>(
            Q, K, attn, SS, SS, DK, DM, DM, SS, 0.125f, nullptr, nullptr,
            NH,
            /*A*/ (long long)DK, (long long)SS * DM,
            /*B*/ (long long)DK, (long long)SS * DM,
            /*C*/ (long long)SS * SS, (long long)NH * SS * SS);
    }

    // 3) softmax rows
    softmax_k<<<BB * NH * SS, thr>>>(attn);

    // 4) context = attn @ V_h, batched  (M=2048,N=64,K=2048)
    {
        dim3 grid(1, SS / 128, BB * NH);
        gemm_k<128,64,16,8,4,false,0><<<grid, thr>>>(
            attn, V, ctx, SS, DK, SS, SS, DM, DM, 1.0f, nullptr, nullptr,
            NH,
            /*A*/ (long long)SS * SS, (long long)NH * SS * SS,
            /*B*/ (long long)DK, (long long)SS * DM,
            /*C*/ (long long)DK, (long long)SS * DM);
    }

    // 5) attn_out + residual: tmp = ctx @ w_o + b_o + x
    {
        dim3 grid(DM / 128, BS / 128, 1);
        gemm_k<128,128,8,8,8,false,0><<<grid, thr>>>(
            ctx, w_o, tmp, BS, DM, DM, DM, DM, DM, 1.0f, b_o, x,
            1, 0,0, 0,0, 0,0);
    }

    // 6) h = LN1(tmp)
    ln_k<<<BS, thr>>>(tmp, ln1g, ln1b, h);

    // 7) ff = gelu(h @ w1 + b1)   (M=4096,N=4096,K=1024)
    {
        dim3 grid(DFF / 128, BS / 128, 1);
        gemm_k<128,128,8,8,8,false,1><<<grid, thr>>>(
            h, w1, ff, BS, DFF, DM, DM, DFF, DFF, 1.0f, b1, nullptr,
            1, 0,0, 0,0, 0,0);
    }

    // 8) tmp = ff @ w2 + b2 + h   (M=4096,N=1024,K=4096)
    {
        dim3 grid(DM / 128, BS / 128, 1);
        gemm_k<128,128,8,8,8,false,0><<<grid, thr>>>(
            ff, w2, tmp, BS, DM, DFF, DFF, DM, DM, 1.0f, b2, h,
            1, 0,0, 0,0, 0,0);
    }

    // 9) out = LN2(tmp)
    ln_k<<<BS, thr>>>(tmp, ln2g, ln2b, out);
}

// round 4
// speedup vs baseline: 1.3638x; 1.3638x over previous
#include <cuda_runtime.h>
#include <math.h>

// Problem constants
#define BB      2
#define SS      2048
#define DM      1024
#define NH      16
#define DK      64
#define DFF     4096
#define BS      (BB*SS)               // 4096 rows
#define OUT_ELEMS ((long long)BS*DM)              // 4194304
#define ATT_ELEMS ((long long)BB*NH*SS*SS)        // 134217728

// ---------------- scratch (no allocation allowed -> __device__ globals) ----
__device__ float g_Q  [BS*DM];
__device__ float g_K  [BS*DM];
__device__ float g_V  [BS*DM];
__device__ float g_ctx[BS*DM];
__device__ float g_h  [BS*DM];
__device__ float g_tmp[BS*DM];
__device__ float g_ff [(long long)BS*DFF];
__device__ float g_attn_fb[ATT_ELEMS];

// ---------------------------------------------------------------------------
// FMA-only exp (avoids MUFU EX2 which is rt=8/SMSP and becomes the chip
// bottleneck at 134M exps). x <= 0 in softmax use. |rel err| ~ 2e-6.
// ---------------------------------------------------------------------------
__device__ __forceinline__ float fexp(float x) {
    float z  = x * 1.4426950408889634f;      // x * log2(e)
    int   ei = __float2int_rn(z);
    float f  = z - (float)ei;                // f in [-0.5, 0.5]
    float p  =              1.3333558146e-3f;
    p = fmaf(p, f, 9.6181291076e-3f);
    p = fmaf(p, f, 5.5504108665e-2f);
    p = fmaf(p, f, 2.4022650696e-1f);
    p = fmaf(p, f, 6.9314718056e-1f);
    p = fmaf(p, f, 1.0f);
    float r = __int_as_float(__float_as_int(p) + (ei << 23));
    return (x < -87.0f) ? 0.0f : r;
}

__device__ __forceinline__ float gelu_exact(float v) {
    return 0.5f * v * (1.0f + erff(v * 0.70710678118654752f));
}

// ---------------------------------------------------------------------------
// Double-buffered, software-pipelined SGEMM.
// C = act(alpha * A @ B(^T) + bias + res), batched via blockIdx.z.
// All dims divide tiles exactly (true for every call here).
// ---------------------------------------------------------------------------
template<int BM, int BN, int BK, int TM, int TN, bool TRANSB, int ACT>
__global__ void __launch_bounds__((BM/TM)*(BN/TN), 2)
gemm2(const float* __restrict__ A, const float* __restrict__ Bm,
      float* __restrict__ C,
      int K, int lda, int ldb, int ldc,
      float alpha,
      const float* __restrict__ bias,
      const float* __restrict__ res,
      int HH,
      long long sAi, long long sAo,
      long long sBi, long long sBo,
      long long sCi, long long sCo)
{
    constexpr int THREADS = (BM/TM)*(BN/TN);
    constexpr int PAD = 4;
    constexpr int AQ = (BM*BK/4)/THREADS;   // float4 loads per thread for A tile
    constexpr int BQ = (BK*BN/4)/THREADS;   // float4 loads per thread for B tile

    __shared__ float As[2][BK][BM+PAD];
    __shared__ float Bs[2][BK][BN+PAD];

    const int z  = blockIdx.z;
    const int zi = z % HH, zo = z / HH;
    A  += zi * sAi + zo * sAo;
    Bm += zi * sBi + zo * sBo;
    C  += zi * sCi + zo * sCo;
    const float* Rp = res ? (res + zi * sCi + zo * sCo) : nullptr;

    const int m0  = blockIdx.y * BM;
    const int n0  = blockIdx.x * BN;
    const int tid = threadIdx.x;
    const int tx  = tid % (BN / TN);
    const int ty  = tid / (BN / TN);

    float4 a_st[AQ], b_st[BQ];

    auto ldTiles = [&](int k0) {
#pragma unroll
        for (int i = 0; i < AQ; i++) {
            int lin = tid + i * THREADS;
            int row = lin / (BK/4), kq = lin % (BK/4);
            a_st[i] = *reinterpret_cast<const float4*>(
                &A[(size_t)(m0 + row) * lda + k0 + kq * 4]);
        }
        if (TRANSB) {
#pragma unroll
            for (int i = 0; i < BQ; i++) {
                int lin = tid + i * THREADS;
                int row = lin / (BK/4), kq = lin % (BK/4);
                b_st[i] = *reinterpret_cast<const float4*>(
                    &Bm[(size_t)(n0 + row) * ldb + k0 + kq * 4]);
            }
        } else {
#pragma unroll
            for (int i = 0; i < BQ; i++) {
                int lin = tid + i * THREADS;
                int row = lin / (BN/4), nq = lin % (BN/4);
                b_st[i] = *reinterpret_cast<const float4*>(
                    &Bm[(size_t)(k0 + row) * ldb + n0 + nq * 4]);
            }
        }
    };

    auto stTiles = [&](int s) {
#pragma unroll
        for (int i = 0; i < AQ; i++) {
            int lin = tid + i * THREADS;
            int row = lin / (BK/4), kq = lin % (BK/4);
            As[s][kq*4+0][row] = a_st[i].x;
            As[s][kq*4+1][row] = a_st[i].y;
            As[s][kq*4+2][row] = a_st[i].z;
            As[s][kq*4+3][row] = a_st[i].w;
        }
        if (TRANSB) {
#pragma unroll
            for (int i = 0; i < BQ; i++) {
                int lin = tid + i * THREADS;
                int row = lin / (BK/4), kq = lin % (BK/4);
                Bs[s][kq*4+0][row] = b_st[i].x;
                Bs[s][kq*4+1][row] = b_st[i].y;
                Bs[s][kq*4+2][row] = b_st[i].z;
                Bs[s][kq*4+3][row] = b_st[i].w;
            }
        } else {
#pragma unroll
            for (int i = 0; i < BQ; i++) {
                int lin = tid + i * THREADS;
                int row = lin / (BN/4), nq = lin % (BN/4);
                *reinterpret_cast<float4*>(&Bs[s][row][nq*4]) = b_st[i];
            }
        }
    };

    float acc[TM][TN];
#pragma unroll
    for (int i = 0; i < TM; i++)
#pragma unroll
        for (int j = 0; j < TN; j++) acc[i][j] = 0.0f;

    auto comp = [&](int s) {
#pragma unroll
        for (int kk = 0; kk < BK; kk++) {
            float ra[TM], rb[TN];
            const float4* a4 = reinterpret_cast<const float4*>(&As[s][kk][ty * TM]);
#pragma unroll
            for (int i = 0; i < TM / 4; i++) {
                float4 t = a4[i];
                ra[4*i+0] = t.x; ra[4*i+1] = t.y; ra[4*i+2] = t.z; ra[4*i+3] = t.w;
            }
            const float4* b4 = reinterpret_cast<const float4*>(&Bs[s][kk][tx * TN]);
#pragma unroll
            for (int j = 0; j < TN / 4; j++) {
                float4 t = b4[j];
                rb[4*j+0] = t.x; rb[4*j+1] = t.y; rb[4*j+2] = t.z; rb[4*j+3] = t.w;
            }
#pragma unroll
            for (int i = 0; i < TM; i++)
#pragma unroll
                for (int j = 0; j < TN; j++)
                    acc[i][j] = fmaf(ra[i], rb[j], acc[i][j]);
        }
    };

    // prologue
    ldTiles(0);
    stTiles(0);
    __syncthreads();

    const int nT = K / BK;
    int s = 0;
    for (int t = 1; t < nT; t++) {
        ldTiles(t * BK);      // LDG in flight while we compute
        comp(s);
        stTiles(s ^ 1);       // waits on LDG scoreboard
        __syncthreads();
        s ^= 1;
    }
    comp(s);

    // epilogue (vectorized stores; n0+tx*TN is 4-aligned, ldc % 4 == 0)
#pragma unroll
    for (int i = 0; i < TM; i++) {
        const int m = m0 + ty * TM + i;
#pragma unroll
        for (int j = 0; j < TN; j += 4) {
            const int n = n0 + tx * TN + j;
            float4 v;
            float* vp = &v.x;
#pragma unroll
            for (int q = 0; q < 4; q++) {
                float t = acc[i][j+q] * alpha;
                if (bias) t += bias[n + q];
                if (Rp)   t += Rp[(size_t)m * ldc + n + q];
                if (ACT == 1) t = gelu_exact(t);
                vp[q] = t;
            }
            *reinterpret_cast<float4*>(&C[(size_t)m * ldc + n]) = v;
        }
    }
}

// ---------------------------------------------------------------------------
// Row softmax over S=2048, in place. One block/row, 256 threads,
// 8 elements per thread kept in registers; FMA-only exp.
// ---------------------------------------------------------------------------
__global__ void __launch_bounds__(256) softmax_k(float* __restrict__ attn)
{
    const int tid = threadIdx.x;
    float4* p = reinterpret_cast<float4*>(attn + (long long)blockIdx.x * SS);

    float4 v0 = p[tid];
    float4 v1 = p[tid + 256];

    __shared__ float red[8];

    float lm = fmaxf(fmaxf(fmaxf(v0.x, v0.y), fmaxf(v0.z, v0.w)),
                     fmaxf(fmaxf(v1.x, v1.y), fmaxf(v1.z, v1.w)));
#pragma unroll
    for (int o = 16; o > 0; o >>= 1)
        lm = fmaxf(lm, __shfl_xor_sync(0xffffffffu, lm, o));
    if ((tid & 31) == 0) red[tid >> 5] = lm;
    __syncthreads();
    if (tid < 8) {
        float v = red[tid];
#pragma unroll
        for (int o = 4; o > 0; o >>= 1)
            v = fmaxf(v, __shfl_xor_sync(0xffu, v, o));
        if (tid == 0) red[0] = v;
    }
    __syncthreads();
    const float mx = red[0];
    __syncthreads();   // red[] reused below

    v0.x = fexp(v0.x - mx); v0.y = fexp(v0.y - mx);
    v0.z = fexp(v0.z - mx); v0.w = fexp(v0.w - mx);
    v1.x = fexp(v1.x - mx); v1.y = fexp(v1.y - mx);
    v1.z = fexp(v1.z - mx); v1.w = fexp(v1.w - mx);

    float ls = (v0.x + v0.y + v0.z + v0.w) + (v1.x + v1.y + v1.z + v1.w);
#pragma unroll
    for (int o = 16; o > 0; o >>= 1)
        ls += __shfl_xor_sync(0xffffffffu, ls, o);
    if ((tid & 31) == 0) red[tid >> 5] = ls;
    __syncthreads();
    if (tid < 8) {
        float v = red[tid];
#pragma unroll
        for (int o = 4; o > 0; o >>= 1)
            v += __shfl_xor_sync(0xffu, v, o);
        if (tid == 0) red[0] = v;
    }
    __syncthreads();
    const float inv = 1.0f / red[0];

    v0.x *= inv; v0.y *= inv; v0.z *= inv; v0.w *= inv;
    v1.x *= inv; v1.y *= inv; v1.z *= inv; v1.w *= inv;
    p[tid]       = v0;
    p[tid + 256] = v1;
}

// ---------------------------------------------------------------------------
// LayerNorm over D=1024, one block (256 threads) per row. EPS = 1e-5.
// ---------------------------------------------------------------------------
__global__ void __launch_bounds__(256)
ln_k(const float* __restrict__ in, const float* __restrict__ gam,
     const float* __restrict__ bet, float* __restrict__ out)
{
    const int row = blockIdx.x;
    const int tid = threadIdx.x;
    const float* p = in + (size_t)row * DM;

    float v[4];
    float s = 0.0f, ss = 0.0f;
#pragma unroll
    for (int i = 0; i < 4; i++) {
        v[i] = p[tid + i * 256];
        s  += v[i];
        ss += v[i] * v[i];
    }
    __shared__ float r1[8], r2[8];
#pragma unroll
    for (int o = 16; o > 0; o >>= 1) {
        s  += __shfl_xor_sync(0xffffffffu, s,  o);
        ss += __shfl_xor_sync(0xffffffffu, ss, o);
    }
    if ((tid & 31) == 0) { r1[tid >> 5] = s; r2[tid >> 5] = ss; }
    __syncthreads();
    if (tid < 8) {
        float a = r1[tid], b = r2[tid];
#pragma unroll
        for (int o = 4; o > 0; o >>= 1) {
            a += __shfl_xor_sync(0xffu, a, o);
            b += __shfl_xor_sync(0xffu, b, o);
        }
        if (tid == 0) { r1[0] = a; r2[0] = b; }
    }
    __syncthreads();
    const float mean = r1[0] * (1.0f / DM);
    const float var  = r2[0] * (1.0f / DM) - mean * mean;
    const float rstd = rsqrtf(var + 1e-5f);
    float* o = out + (size_t)row * DM;
#pragma unroll
    for (int i = 0; i < 4; i++) {
        int c = tid + i * 256;
        o[c] = (v[i] - mean) * rstd * gam[c] + bet[c];
    }
}

// ---------------------------------------------------------------------------
extern "C" void kernel_launch(void* const* d_in, const int* in_sizes, int n_in,
                              void* d_out, int out_size)
{
    const float* x    = (const float*)d_in[0];
    const float* w_q  = (const float*)d_in[1];
    const float* w_k  = (const float*)d_in[2];
    const float* w_v  = (const float*)d_in[3];
    const float* w_o  = (const float*)d_in[4];
    const float* b_o  = (const float*)d_in[5];
    const float* w1   = (const float*)d_in[6];
    const float* b1   = (const float*)d_in[7];
    const float* w2   = (const float*)d_in[8];
    const float* b2   = (const float*)d_in[9];
    const float* ln1g = (const float*)d_in[10];
    const float* ln1b = (const float*)d_in[11];
    const float* ln2g = (const float*)d_in[12];
    const float* ln2b = (const float*)d_in[13];
    float* out = (float*)d_out;

    float *Q, *K, *V, *ctx, *h, *tmp, *ff, *attn_fb;
    cudaGetSymbolAddress((void**)&Q,       g_Q);
    cudaGetSymbolAddress((void**)&K,       g_K);
    cudaGetSymbolAddress((void**)&V,       g_V);
    cudaGetSymbolAddress((void**)&ctx,     g_ctx);
    cudaGetSymbolAddress((void**)&h,       g_h);
    cudaGetSymbolAddress((void**)&tmp,     g_tmp);
    cudaGetSymbolAddress((void**)&ff,      g_ff);
    cudaGetSymbolAddress((void**)&attn_fb, g_attn_fb);

    float* attn = ((long long)out_size >= OUT_ELEMS + ATT_ELEMS)
                      ? (out + OUT_ELEMS) : attn_fb;

    // 1) QKV projections (M=4096, N=1024, K=1024)
    {
        dim3 grid(DM / 128, BS / 128, 1);
        gemm2<128,128,16,8,8,false,0><<<grid, 256>>>(
            x, w_q, Q, DM, DM, DM, DM, 1.0f, nullptr, nullptr,
            1, 0,0, 0,0, 0,0);
        gemm2<128,128,16,8,8,false,0><<<grid, 256>>>(
            x, w_k, K, DM, DM, DM, DM, 1.0f, nullptr, nullptr,
            1, 0,0, 0,0, 0,0);
        gemm2<128,128,16,8,8,false,0><<<grid, 256>>>(
            x, w_v, V, DM, DM, DM, DM, 1.0f, nullptr, nullptr,
            1, 0,0, 0,0, 0,0);
    }

    // 2) scores = Q_h @ K_h^T / 8, batched over 32 (b,h).  K=64.
    {
        dim3 grid(SS / 128, SS / 128, BB * NH);
        gemm2<128,128,16,8,8,true,0><<<grid, 256>>>(
            Q, K, attn, DK, DM, DM, SS, 0.125f, nullptr, nullptr,
            NH,
            (long long)DK, (long long)SS * DM,
            (long long)DK, (long long)SS * DM,
            (long long)SS * SS, (long long)NH * SS * SS);
    }

    // 3) softmax rows
    softmax_k<<<BB * NH * SS, 256>>>(attn);

    // 4) context = attn @ V_h, batched  (M=2048, N=64, K=2048)
    {
        dim3 grid(1, SS / 128, BB * NH);
        gemm2<128,64,16,8,8,false,0><<<grid, 128>>>(
            attn, V, ctx, SS, SS, DM, DM, 1.0f, nullptr, nullptr,
            NH,
            (long long)SS * SS, (long long)NH * SS * SS,
            (long long)DK, (long long)SS * DM,
            (long long)DK, (long long)SS * DM);
    }

    // 5) tmp = ctx @ w_o + b_o + x
    {
        dim3 grid(DM / 128, BS / 128, 1);
        gemm2<128,128,16,8,8,false,0><<<grid, 256>>>(
            ctx, w_o, tmp, DM, DM, DM, DM, 1.0f, b_o, x,
            1, 0,0, 0,0, 0,0);
    }

    // 6) h = LN1(tmp)
    ln_k<<<BS, 256>>>(tmp, ln1g, ln1b, h);

    // 7) ff = gelu(h @ w1 + b1)   (M=4096, N=4096, K=1024)
    {
        dim3 grid(DFF / 128, BS / 128, 1);
        gemm2<128,128,16,8,8,false,1><<<grid, 256>>>(
            h, w1, ff, DM, DM, DFF, DFF, 1.0f, b1, nullptr,
            1, 0,0, 0,0, 0,0);
    }

    // 8) tmp = ff @ w2 + b2 + h   (M=4096, N=1024, K=4096)
    {
        dim3 grid(DM / 128, BS / 128, 1);
        gemm2<128,128,16,8,8,false,0><<<grid, 256>>>(
            ff, w2, tmp, DFF, DFF, DM, DM, 1.0f, b2, h,
            1, 0,0, 0,0, 0,0);
    }

    // 9) out = LN2(tmp)
    ln_k<<<BS, 256>>>(tmp, ln2g, ln2b, out);
}